// round 13
// baseline (speedup 1.0000x reference)
#include <cuda_runtime.h>
#include <cuda_fp16.h>
#include <cstdint>

// Problem constants
#define B_  4
#define T_  4096
#define C_  1024
#define H_  64
#define BT_ (B_*T_)

typedef unsigned long long u64;
typedef unsigned int u32;

// Scratch — device globals, no allocation.
__device__ __half g_kh[(size_t)BT_ * H_];   // k, fp16 [b][t][h]
__device__ __half g_qh[(size_t)BT_ * H_];   // q, fp16 [b][t][h]
__device__ __half g_vt[(size_t)H_ * BT_];   // v^T, fp16 [h][b*T+t]
__device__ __half g_wh[192 * C_];           // fp16 W (k|q|v rows)
__device__ float  g_p[6][(size_t)BT_ * H_]; // partial O per key-segment slot
__device__ float  g_l[6][(size_t)BT_];      // partial lsum per slot
__device__ u32    g_cnt[128];               // per-(b,mblk) arrival counters

// ---------------- helpers ----------------
__device__ __forceinline__ u32 pack16(float hi, float lo) {
    u32 d; asm("cvt.rn.f16x2.f32 %0, %1, %2;" : "=r"(d) : "f"(hi), "f"(lo)); return d;
}
__device__ __forceinline__ u32 ex2h2(float hi, float lo) {
    u32 x = pack16(hi, lo);
    u32 y; asm("ex2.approx.f16x2 %0, %1;" : "=r"(y) : "r"(x));
    return y;
}
__device__ __forceinline__ void mma_f16(
    float& d0, float& d1, float& d2, float& d3,
    u32 a0, u32 a1, u32 a2, u32 a3, u32 b0, u32 b1)
{
    asm volatile(
        "mma.sync.aligned.m16n8k16.row.col.f32.f16.f16.f32 "
        "{%0,%1,%2,%3}, {%4,%5,%6,%7}, {%8,%9}, {%0,%1,%2,%3};"
        : "+f"(d0), "+f"(d1), "+f"(d2), "+f"(d3)
        : "r"(a0), "r"(a1), "r"(a2), "r"(a3), "r"(b0), "r"(b1));
}
__device__ __forceinline__ u32 smem_u32(const void* p) {
    u32 a;
    asm("{ .reg .u64 t; cvta.to.shared.u64 t, %1; cvt.u32.u64 %0, t; }" : "=r"(a) : "l"(p));
    return a;
}
#define LDSM4(R0, R1, R2, R3, A) \
    asm volatile("ldmatrix.sync.aligned.m8n8.x4.shared.b16 {%0,%1,%2,%3}, [%4];" \
        : "=r"(R0), "=r"(R1), "=r"(R2), "=r"(R3) : "r"(A))
#define CP16(dst, src) asm volatile("cp.async.ca.shared.global [%0], [%1], 16;" :: "r"(dst), "l"(src) : "memory")
#define CP_COMMIT()    asm volatile("cp.async.commit_group;" ::: "memory")
#define CP_WAIT0()     asm volatile("cp.async.wait_group 0;" ::: "memory")
#define CP_WAIT1()     asm volatile("cp.async.wait_group 1;" ::: "memory")

#define LOG2E64 0.02254211001389006f    /* log2(e)/64 */
#define NEGBIG  (-1e30f)

// =================================================================
// Kernel 0: convert W (Wk|Wq|Wv) to fp16, store concatenated.
// =================================================================
__global__ void __launch_bounds__(256) w_cvt(
    const float* __restrict__ Wk, const float* __restrict__ Wq,
    const float* __restrict__ Wv)
{
    int f = blockIdx.x * 256 + threadIdx.x;
    int head = f >> 14;
    int off  = f & 16383;
    const float4* src = (const float4*)(head == 0 ? Wk : (head == 1 ? Wq : Wv));
    float4 v = src[off];
    uint2 u;
    u.x = pack16(v.y, v.x);
    u.y = pack16(v.w, v.z);
    ((uint2*)g_wh)[f] = u;
}

// =================================================================
// Kernel 1: fused QKV projection, fp16 mma + ldmatrix (unchanged).
// =================================================================
#define PST 36                                   // u32 stride per row
#define PROJ_STAGE ((128 + 192) * PST)
#define PROJ_SMEM  (PROJ_STAGE * 2 * 4)

__global__ void __launch_bounds__(256, 1) proj_mma(const float* __restrict__ x)
{
    extern __shared__ u32 psm[];
    const u32 smb = smem_u32(psm);

    const int tid  = threadIdx.x;
    const int w    = tid >> 5;
    const int lane = tid & 31;
    const int lq   = lane >> 2;
    const int lk   = lane & 3;
    const int grp  = lane >> 3;
    const int lrow = lane & 7;
    const int wrow = w >> 1;
    const int wcol = w & 1;
    const int m0   = blockIdx.x * 128;

    const u32 abase = (u32)((((grp & 1) * 8 + lrow) * PST + (grp >> 1) * 4) * 4);
    const u32 bbase = (u32)((((grp >> 1) * 8 + lrow) * PST + (grp & 1) * 4) * 4);
    const u32 xwarp = (u32)(wrow * 32 * PST * 4);
    const u32 wwarp = (u32)((128 + wcol * 96) * PST * 4);

    float acc[2][12][4];
#pragma unroll
    for (int mi = 0; mi < 2; mi++)
#pragma unroll
        for (int nt = 0; nt < 12; nt++)
#pragma unroll
            for (int e = 0; e < 4; e++) acc[mi][nt][e] = 0.0f;

#define PROJ_FILL(SB, CH) do {                                               \
    u32* xs_ = (SB);                                                         \
    u32  wsa_ = smem_u32((SB) + 128 * PST);                                  \
    _Pragma("unroll")                                                        \
    for (int i_ = 0; i_ < 6; i_++) {                                         \
        int idx_ = tid + i_ * 256;                                           \
        int r_ = idx_ >> 3, c8_ = idx_ & 7;                                  \
        CP16(wsa_ + (u32)(r_ * PST + c8_ * 4) * 4,                           \
             (const void*)(g_wh + (size_t)r_ * C_ + (CH) * 64 + c8_ * 8));   \
    }                                                                        \
    _Pragma("unroll")                                                        \
    for (int i_ = 0; i_ < 8; i_++) {                                         \
        int idx_ = tid + i_ * 256;                                           \
        int r_ = idx_ >> 4, c4_ = idx_ & 15;                                 \
        float4 v_ = *(const float4*)(x + (size_t)(m0 + r_) * C_ + (CH) * 64 + c4_ * 4); \
        uint2 u_;                                                            \
        u_.x = pack16(v_.y, v_.x);                                           \
        u_.y = pack16(v_.w, v_.z);                                           \
        *(uint2*)(xs_ + r_ * PST + c4_ * 2) = u_;                            \
    }                                                                        \
    CP_COMMIT();                                                             \
} while (0)

    PROJ_FILL(psm, 0);
    CP_WAIT0();
    __syncthreads();

    for (int ch = 0; ch < 16; ch++) {
        const int cur = ch & 1;
        if (ch + 1 < 16) {
            u32* nb = psm + ((ch + 1) & 1) * PROJ_STAGE;
            PROJ_FILL(nb, ch + 1);
        }
        {
            const u32 sbyte = smb + (u32)cur * (PROJ_STAGE * 4);
#pragma unroll
            for (int ks = 0; ks < 4; ks++) {
                u32 a[2][4];
                LDSM4(a[0][0], a[0][1], a[0][2], a[0][3],
                      sbyte + xwarp + abase + (u32)(ks * 32));
                LDSM4(a[1][0], a[1][1], a[1][2], a[1][3],
                      sbyte + xwarp + abase + (u32)(ks * 32 + 16 * PST * 4));
#pragma unroll
                for (int ntp = 0; ntp < 6; ntp++) {
                    u32 r0, r1, r2, r3;
                    LDSM4(r0, r1, r2, r3,
                          sbyte + wwarp + bbase + (u32)(ntp * 16 * PST * 4 + ks * 32));
                    mma_f16(acc[0][2*ntp][0], acc[0][2*ntp][1], acc[0][2*ntp][2], acc[0][2*ntp][3],
                            a[0][0], a[0][1], a[0][2], a[0][3], r0, r1);
                    mma_f16(acc[1][2*ntp][0], acc[1][2*ntp][1], acc[1][2*ntp][2], acc[1][2*ntp][3],
                            a[1][0], a[1][1], a[1][2], a[1][3], r0, r1);
                    mma_f16(acc[0][2*ntp+1][0], acc[0][2*ntp+1][1], acc[0][2*ntp+1][2], acc[0][2*ntp+1][3],
                            a[0][0], a[0][1], a[0][2], a[0][3], r2, r3);
                    mma_f16(acc[1][2*ntp+1][0], acc[1][2*ntp+1][1], acc[1][2*ntp+1][2], acc[1][2*ntp+1][3],
                            a[1][0], a[1][1], a[1][2], a[1][3], r2, r3);
                }
            }
        }
        if (ch + 1 < 16) CP_WAIT0();
        __syncthreads();
    }

    // ---- epilogue: fp16 round; k/q row-major, v transposed ----
#pragma unroll
    for (int mi = 0; mi < 2; mi++) {
#pragma unroll
        for (int nt = 0; nt < 12; nt++) {
            int gr = m0 + wrow * 32 + mi * 16 + lq;
            int gh = wcol * 96 + nt * 8 + 2 * lk;
            int head = gh >> 6;
            int hc   = gh & 63;
            if (head < 2) {
                __half* op = head ? g_qh : g_kh;
                *(u32*)(op + (size_t)gr * H_ + hc)       = pack16(acc[mi][nt][1], acc[mi][nt][0]);
                *(u32*)(op + (size_t)(gr + 8) * H_ + hc) = pack16(acc[mi][nt][3], acc[mi][nt][2]);
            } else {
                g_vt[(size_t)hc * BT_ + gr]           = __float2half_rn(acc[mi][nt][0]);
                g_vt[(size_t)(hc + 1) * BT_ + gr]     = __float2half_rn(acc[mi][nt][1]);
                g_vt[(size_t)hc * BT_ + gr + 8]       = __float2half_rn(acc[mi][nt][2]);
                g_vt[(size_t)(hc + 1) * BT_ + gr + 8] = __float2half_rn(acc[mi][nt][3]);
            }
        }
    }
}

// =================================================================
// Kernel 2: attention + fused normalize. 128 q-rows/CTA, 4 warps x
//   32 rows. Uniform <=12-tile segments (428 CTAs, single wave).
//   fp16 mma + ldmatrix + ex2 (mask-free fast path) + ones-MMA.
//   Last segment CTA per q-block combines slots and writes out.
// =================================================================
#define KTILE 64
#define TSEG  12
#define SEGS_PB 107
#define AST 36
#define STG_WORDS (KTILE * AST * 2)
#define STG_BYTES (STG_WORDS * 4)
#define ATTN_SMEM (STG_BYTES * 2)

__global__ void __launch_bounds__(128, 3) attn_mma(float* __restrict__ out)
{
    extern __shared__ u32 smw[];
    const u32 smb = smem_u32(smw);
    __shared__ u32 s_last;

    const int tid  = threadIdx.x;
    const int w    = tid >> 5;
    const int lane = tid & 31;
    const int lq   = lane >> 2;
    const int lk   = lane & 3;
    const int grp  = lane >> 3;
    const int lrow = lane & 7;

    // ---- segment -> (b, mblk, tile range) ----
    const int b = blockIdx.x / SEGS_PB;
    int s = blockIdx.x - b * SEGS_PB;
    int mblk = 0, nm = 3;
#pragma unroll 1
    for (int m = 0; m < 32; m++) {
        int n  = min(2 * m + 3, T_ / KTILE);
        int ns_ = (n + TSEG - 1) / TSEG;
        if (s < ns_) { mblk = m; nm = n; break; }
        s -= ns_;
    }
    const int slot  = s;
    const int ns    = (nm + TSEG - 1) / TSEG;
    const int m0    = mblk * 128;
    const int t_beg = s * TSEG;
    const int t_end = min(t_beg + TSEG, nm);

    const int qbase = m0 + w * 32;
    const int qa0   = qbase + lq;

    const u32 lmb = (u32)(((((grp >> 1) * 8 + lrow) * AST) + (grp & 1) * 4) * 4);
    const u32 bone = (lq == 0) ? 0x3C003C00u : 0u;

    // ---- Q A-frags fp16, 4 k-steps x 2 row-halves ----
    u32 qf[2][4][4];
#pragma unroll
    for (int mi = 0; mi < 2; mi++) {
        const u32* qp = (const u32*)(g_qh + ((size_t)b * T_ + qa0 + mi * 16) * H_) + lk;
#pragma unroll
        for (int ks = 0; ks < 4; ks++) {
            qf[mi][ks][0] = qp[ks * 8];
            qf[mi][ks][1] = qp[8 * 32 + ks * 8];
            qf[mi][ks][2] = qp[ks * 8 + 4];
            qf[mi][ks][3] = qp[8 * 32 + ks * 8 + 4];
        }
    }

    float oc[2][9][4];     // [..][8] = lsum column accumulator
#pragma unroll
    for (int mi = 0; mi < 2; mi++)
#pragma unroll
        for (int i = 0; i < 9; i++)
#pragma unroll
            for (int j = 0; j < 4; j++) oc[mi][i][j] = 0.0f;

#define ATTN_FILL(STG, T) do {                                               \
    const __half* kg_ = g_kh + ((size_t)b * T_ + (size_t)(T) * KTILE) * H_;  \
    const __half* vg_ = g_vt + (size_t)b * T_ + (size_t)(T) * KTILE;         \
    u32 base_ = smb + (u32)(STG) * STG_BYTES;                                \
    _Pragma("unroll")                                                        \
    for (int i_ = 0; i_ < 4; i_++) {                                         \
        int idx_ = tid + i_ * 128;                                           \
        int r_ = idx_ >> 3, c8_ = idx_ & 7;                                  \
        CP16(base_ + (u32)(r_ * AST + c8_ * 4) * 4,                          \
             (const void*)(kg_ + (size_t)r_ * H_ + c8_ * 8));                \
        CP16(base_ + (u32)(KTILE * AST + r_ * AST + c8_ * 4) * 4,            \
             (const void*)(vg_ + (size_t)r_ * BT_ + c8_ * 8));               \
    }                                                                        \
    CP_COMMIT();                                                             \
} while (0)

    ATTN_FILL(t_beg & 1, t_beg);

    for (int t = t_beg; t < t_end; t++) {
        const int j0 = t * KTILE;
        const bool pre = (t + 1 < t_end);
        if (pre) {
            ATTN_FILL((t + 1) & 1, t + 1);
            CP_WAIT1();
        } else {
            CP_WAIT0();
        }
        __syncthreads();

        const u32 kbyte = smb + (u32)(t & 1) * STG_BYTES;
        const u32 vbyte = kbyte + (u32)(KTILE * AST * 4);

        const int ktmax = min(3, (qbase + 32 - j0) >> 4);
#pragma unroll
        for (int kt = 0; kt <= ktmax; kt++) {
            float sg[2][2][4];
#pragma unroll
            for (int g = 0; g < 2; g++)
#pragma unroll
                for (int mi = 0; mi < 2; mi++)
#pragma unroll
                    for (int e = 0; e < 4; e++) sg[g][mi][e] = 0.0f;
#pragma unroll
            for (int ks = 0; ks < 4; ks++) {
                u32 kb0, kb1, kb2, kb3;
                LDSM4(kb0, kb1, kb2, kb3,
                      kbyte + lmb + (u32)(kt * 16 * AST * 4 + ks * 32));
                mma_f16(sg[0][0][0], sg[0][0][1], sg[0][0][2], sg[0][0][3],
                        qf[0][ks][0], qf[0][ks][1], qf[0][ks][2], qf[0][ks][3], kb0, kb1);
                mma_f16(sg[0][1][0], sg[0][1][1], sg[0][1][2], sg[0][1][3],
                        qf[1][ks][0], qf[1][ks][1], qf[1][ks][2], qf[1][ks][3], kb0, kb1);
                mma_f16(sg[1][0][0], sg[1][0][1], sg[1][0][2], sg[1][0][3],
                        qf[0][ks][0], qf[0][ks][1], qf[0][ks][2], qf[0][ks][3], kb2, kb3);
                mma_f16(sg[1][1][0], sg[1][1][1], sg[1][1][2], sg[1][1][3],
                        qf[1][ks][0], qf[1][ks][1], qf[1][ks][2], qf[1][ks][3], kb2, kb3);
            }

            u32 pa[2][4];
            const int cb = j0 + kt * 16;
            if (cb + 14 <= qbase) {
                // all 16 keys valid for every row of this warp — no masks
#pragma unroll
                for (int mi = 0; mi < 2; mi++)
#pragma unroll
                    for (int g = 0; g < 2; g++) {
                        pa[mi][2 * g]     = ex2h2(sg[g][mi][1] * LOG2E64, sg[g][mi][0] * LOG2E64);
                        pa[mi][2 * g + 1] = ex2h2(sg[g][mi][3] * LOG2E64, sg[g][mi][2] * LOG2E64);
                    }
            } else {
#pragma unroll
                for (int mi = 0; mi < 2; mi++) {
                    const int ra = qa0 + mi * 16;
                    const int rb = ra + 8;
#pragma unroll
                    for (int g = 0; g < 2; g++) {
                        const int jb = cb + g * 8 + 2 * lk;
                        float e0 = (jb     <= ra + 1) ? sg[g][mi][0] * LOG2E64 : NEGBIG;
                        float e1 = (jb + 1 <= ra + 1) ? sg[g][mi][1] * LOG2E64 : NEGBIG;
                        float e2 = (jb     <= rb + 1) ? sg[g][mi][2] * LOG2E64 : NEGBIG;
                        float e3 = (jb + 1 <= rb + 1) ? sg[g][mi][3] * LOG2E64 : NEGBIG;
                        pa[mi][2 * g]     = ex2h2(e1, e0);
                        pa[mi][2 * g + 1] = ex2h2(e3, e2);
                    }
                }
            }

#pragma unroll
            for (int otp = 0; otp < 4; otp++) {
                u32 v0, v1, v2, v3;
                LDSM4(v0, v1, v2, v3,
                      vbyte + lmb + (u32)(otp * 16 * AST * 4 + kt * 32));
                mma_f16(oc[0][2*otp][0], oc[0][2*otp][1], oc[0][2*otp][2], oc[0][2*otp][3],
                        pa[0][0], pa[0][1], pa[0][2], pa[0][3], v0, v1);
                mma_f16(oc[1][2*otp][0], oc[1][2*otp][1], oc[1][2*otp][2], oc[1][2*otp][3],
                        pa[1][0], pa[1][1], pa[1][2], pa[1][3], v0, v1);
                mma_f16(oc[0][2*otp+1][0], oc[0][2*otp+1][1], oc[0][2*otp+1][2], oc[0][2*otp+1][3],
                        pa[0][0], pa[0][1], pa[0][2], pa[0][3], v2, v3);
                mma_f16(oc[1][2*otp+1][0], oc[1][2*otp+1][1], oc[1][2*otp+1][2], oc[1][2*otp+1][3],
                        pa[1][0], pa[1][1], pa[1][2], pa[1][3], v2, v3);
            }
            mma_f16(oc[0][8][0], oc[0][8][1], oc[0][8][2], oc[0][8][3],
                    pa[0][0], pa[0][1], pa[0][2], pa[0][3], bone, bone);
            mma_f16(oc[1][8][0], oc[1][8][1], oc[1][8][2], oc[1][8][3],
                    pa[1][0], pa[1][1], pa[1][2], pa[1][3], bone, bone);
        }
        __syncthreads();
    }

    // =============== fused epilogue ===============
    if (ns == 1) {
        // single segment: normalize in-register and write out directly
#pragma unroll
        for (int mi = 0; mi < 2; mi++) {
            float la = __shfl_sync(0xffffffffu, oc[mi][8][0], lane & ~3);
            float lb = __shfl_sync(0xffffffffu, oc[mi][8][2], lane & ~3);
            float ia = 1.0f / la;
            float ib = 1.0f / lb;
            float* ra = out + ((size_t)b * T_ + qa0 + mi * 16) * H_ + 2 * lk;
            float* rb = ra + (size_t)8 * H_;
#pragma unroll
            for (int ot = 0; ot < 8; ot++) {
                *(float2*)(ra + ot * 8) = make_float2(oc[mi][ot][0] * ia, oc[mi][ot][1] * ia);
                *(float2*)(rb + ot * 8) = make_float2(oc[mi][ot][2] * ib, oc[mi][ot][3] * ib);
            }
        }
        return;
    }

    // ---- write partial lsum + O to slot buffers ----
    float* lp = g_l[slot];
    if (lk == 0) {
        lp[(size_t)b * T_ + qa0]      = oc[0][8][0];
        lp[(size_t)b * T_ + qa0 + 8]  = oc[0][8][2];
        lp[(size_t)b * T_ + qa0 + 16] = oc[1][8][0];
        lp[(size_t)b * T_ + qa0 + 24] = oc[1][8][2];
    }
    float* pp = g_p[slot];
#pragma unroll
    for (int mi = 0; mi < 2; mi++) {
        float* ra = pp + ((size_t)b * T_ + qa0 + mi * 16) * H_ + 2 * lk;
        float* rb = ra + (size_t)8 * H_;
#pragma unroll
        for (int ot = 0; ot < 8; ot++) {
            *(float2*)(ra + ot * 8) = make_float2(oc[mi][ot][0], oc[mi][ot][1]);
            *(float2*)(rb + ot * 8) = make_float2(oc[mi][ot][2], oc[mi][ot][3]);
        }
    }

    // ---- arrival protocol: last segment CTA combines + normalizes ----
    __threadfence();
    __syncthreads();
    const int qb = b * 32 + mblk;
    if (tid == 0) {
        u32 old = atomicAdd(&g_cnt[qb], 1u);
        u32 last = (old == (u32)(ns - 1)) ? 1u : 0u;
        if (last) g_cnt[qb] = 0u;     // reset for next graph replay
        s_last = last;
    }
    __syncthreads();
    if (!s_last) return;

    // finisher: sum slots in fixed order, normalize, write out
#pragma unroll 1
    for (int i = 0; i < 16; i++) {
        int idx  = tid + i * 128;          // 0..2047 float4 of this q-block
        int row  = idx >> 4;
        int c4   = idx & 15;
        size_t grow = (size_t)b * T_ + m0 + row;
        float l = 0.0f;
        float4 a = make_float4(0.f, 0.f, 0.f, 0.f);
#pragma unroll 1
        for (int sl = 0; sl < ns; sl++) {
            l += g_l[sl][grow];
            float4 c = ((const float4*)g_p[sl])[grow * 16 + c4];
            a.x += c.x; a.y += c.y; a.z += c.z; a.w += c.w;
        }
        float inv = 1.0f / l;
        a.x *= inv; a.y *= inv; a.z *= inv; a.w *= inv;
        ((float4*)out)[grow * 16 + c4] = a;
    }
}

// =================================================================
// launch
// =================================================================
extern "C" void kernel_launch(void* const* d_in, const int* in_sizes, int n_in,
                              void* d_out, int out_size)
{
    const float* x  = (const float*)d_in[0];
    const float* Wk = (const float*)d_in[1];
    const float* Wq = (const float*)d_in[2];
    const float* Wv = (const float*)d_in[3];
    float* out = (float*)d_out;

    (void)in_sizes; (void)n_in; (void)out_size;

    cudaFuncSetAttribute(proj_mma, cudaFuncAttributeMaxDynamicSharedMemorySize, PROJ_SMEM);
    cudaFuncSetAttribute(attn_mma, cudaFuncAttributeMaxDynamicSharedMemorySize, ATTN_SMEM);

    w_cvt<<<192, 256>>>(Wk, Wq, Wv);
    proj_mma<<<BT_ / 128, 256, PROJ_SMEM>>>(x);
    attn_mma<<<B_ * SEGS_PB, 128, ATTN_SMEM>>>(out);
}

// round 14
// speedup vs baseline: 1.1965x; 1.1965x over previous
#include <cuda_runtime.h>
#include <cuda_fp16.h>
#include <cstdint>

// Problem constants
#define B_  4
#define T_  4096
#define C_  1024
#define H_  64
#define BT_ (B_*T_)

typedef unsigned long long u64;
typedef unsigned int u32;

// Scratch — device globals, no allocation.
__device__ __half g_kh[(size_t)BT_ * H_];   // k, fp16 [b][t][h]
__device__ __half g_qh[(size_t)BT_ * H_];   // q, fp16 [b][t][h]
__device__ __half g_vt[(size_t)H_ * BT_];   // v^T, fp16 [h][b*T+t]
__device__ __half g_wh[192 * C_];           // fp16 W (k|q|v rows)
__device__ float  g_p[4][(size_t)BT_ * H_]; // partial O per key-quarter
__device__ float  g_l[4][(size_t)BT_];      // partial lsum per quarter

// ---------------- helpers ----------------
__device__ __forceinline__ u32 pack16(float hi, float lo) {
    u32 d; asm("cvt.rn.f16x2.f32 %0, %1, %2;" : "=r"(d) : "f"(hi), "f"(lo)); return d;
}
__device__ __forceinline__ u32 ex2h2(float hi, float lo) {
    u32 x = pack16(hi, lo);
    u32 y; asm("ex2.approx.f16x2 %0, %1;" : "=r"(y) : "r"(x));
    return y;
}
__device__ __forceinline__ void mma_f16(
    float& d0, float& d1, float& d2, float& d3,
    u32 a0, u32 a1, u32 a2, u32 a3, u32 b0, u32 b1)
{
    asm volatile(
        "mma.sync.aligned.m16n8k16.row.col.f32.f16.f16.f32 "
        "{%0,%1,%2,%3}, {%4,%5,%6,%7}, {%8,%9}, {%0,%1,%2,%3};"
        : "+f"(d0), "+f"(d1), "+f"(d2), "+f"(d3)
        : "r"(a0), "r"(a1), "r"(a2), "r"(a3), "r"(b0), "r"(b1));
}
__device__ __forceinline__ u32 smem_u32(const void* p) {
    u32 a;
    asm("{ .reg .u64 t; cvta.to.shared.u64 t, %1; cvt.u32.u64 %0, t; }" : "=r"(a) : "l"(p));
    return a;
}
#define LDSM4(R0, R1, R2, R3, A) \
    asm volatile("ldmatrix.sync.aligned.m8n8.x4.shared.b16 {%0,%1,%2,%3}, [%4];" \
        : "=r"(R0), "=r"(R1), "=r"(R2), "=r"(R3) : "r"(A))
#define CP16(dst, src) asm volatile("cp.async.ca.shared.global [%0], [%1], 16;" :: "r"(dst), "l"(src) : "memory")
#define CP_COMMIT()    asm volatile("cp.async.commit_group;" ::: "memory")
#define CP_WAIT0()     asm volatile("cp.async.wait_group 0;" ::: "memory")
#define CP_WAIT1()     asm volatile("cp.async.wait_group 1;" ::: "memory")

#define LOG2E64 0.02254211001389006f    /* log2(e)/64 */
#define NEGBIG  (-1e30f)

// =================================================================
// Kernel 0: convert W (Wk|Wq|Wv) to fp16 — widened (384 CTAs).
// =================================================================
__global__ void __launch_bounds__(256) w_cvt(
    const float* __restrict__ Wk, const float* __restrict__ Wq,
    const float* __restrict__ Wv)
{
    int f = blockIdx.x * 256 + threadIdx.x;       // float2 index, 98304 total
    int head = f >> 15;                           // 32768 float2 per head
    int off  = f & 32767;
    const float2* src = (const float2*)(head == 0 ? Wk : (head == 1 ? Wq : Wv));
    float2 v = src[off];
    ((u32*)g_wh)[f] = pack16(v.y, v.x);
}

// =================================================================
// Kernel 1: fused QKV projection, fp16 mma + ldmatrix (unchanged).
// =================================================================
#define PST 36                                   // u32 stride per row
#define PROJ_STAGE ((128 + 192) * PST)
#define PROJ_SMEM  (PROJ_STAGE * 2 * 4)

__global__ void __launch_bounds__(256, 1) proj_mma(const float* __restrict__ x)
{
    extern __shared__ u32 psm[];
    const u32 smb = smem_u32(psm);

    const int tid  = threadIdx.x;
    const int w    = tid >> 5;
    const int lane = tid & 31;
    const int lq   = lane >> 2;
    const int lk   = lane & 3;
    const int grp  = lane >> 3;
    const int lrow = lane & 7;
    const int wrow = w >> 1;
    const int wcol = w & 1;
    const int m0   = blockIdx.x * 128;

    const u32 abase = (u32)((((grp & 1) * 8 + lrow) * PST + (grp >> 1) * 4) * 4);
    const u32 bbase = (u32)((((grp >> 1) * 8 + lrow) * PST + (grp & 1) * 4) * 4);
    const u32 xwarp = (u32)(wrow * 32 * PST * 4);
    const u32 wwarp = (u32)((128 + wcol * 96) * PST * 4);

    float acc[2][12][4];
#pragma unroll
    for (int mi = 0; mi < 2; mi++)
#pragma unroll
        for (int nt = 0; nt < 12; nt++)
#pragma unroll
            for (int e = 0; e < 4; e++) acc[mi][nt][e] = 0.0f;

#define PROJ_FILL(SB, CH) do {                                               \
    u32* xs_ = (SB);                                                         \
    u32  wsa_ = smem_u32((SB) + 128 * PST);                                  \
    _Pragma("unroll")                                                        \
    for (int i_ = 0; i_ < 6; i_++) {                                         \
        int idx_ = tid + i_ * 256;                                           \
        int r_ = idx_ >> 3, c8_ = idx_ & 7;                                  \
        CP16(wsa_ + (u32)(r_ * PST + c8_ * 4) * 4,                           \
             (const void*)(g_wh + (size_t)r_ * C_ + (CH) * 64 + c8_ * 8));   \
    }                                                                        \
    _Pragma("unroll")                                                        \
    for (int i_ = 0; i_ < 8; i_++) {                                         \
        int idx_ = tid + i_ * 256;                                           \
        int r_ = idx_ >> 4, c4_ = idx_ & 15;                                 \
        float4 v_ = *(const float4*)(x + (size_t)(m0 + r_) * C_ + (CH) * 64 + c4_ * 4); \
        uint2 u_;                                                            \
        u_.x = pack16(v_.y, v_.x);                                           \
        u_.y = pack16(v_.w, v_.z);                                           \
        *(uint2*)(xs_ + r_ * PST + c4_ * 2) = u_;                            \
    }                                                                        \
    CP_COMMIT();                                                             \
} while (0)

    PROJ_FILL(psm, 0);
    CP_WAIT0();
    __syncthreads();

    for (int ch = 0; ch < 16; ch++) {
        const int cur = ch & 1;
        if (ch + 1 < 16) {
            u32* nb = psm + ((ch + 1) & 1) * PROJ_STAGE;
            PROJ_FILL(nb, ch + 1);
        }
        {
            const u32 sbyte = smb + (u32)cur * (PROJ_STAGE * 4);
#pragma unroll
            for (int ks = 0; ks < 4; ks++) {
                u32 a[2][4];
                LDSM4(a[0][0], a[0][1], a[0][2], a[0][3],
                      sbyte + xwarp + abase + (u32)(ks * 32));
                LDSM4(a[1][0], a[1][1], a[1][2], a[1][3],
                      sbyte + xwarp + abase + (u32)(ks * 32 + 16 * PST * 4));
#pragma unroll
                for (int ntp = 0; ntp < 6; ntp++) {
                    u32 r0, r1, r2, r3;
                    LDSM4(r0, r1, r2, r3,
                          sbyte + wwarp + bbase + (u32)(ntp * 16 * PST * 4 + ks * 32));
                    mma_f16(acc[0][2*ntp][0], acc[0][2*ntp][1], acc[0][2*ntp][2], acc[0][2*ntp][3],
                            a[0][0], a[0][1], a[0][2], a[0][3], r0, r1);
                    mma_f16(acc[1][2*ntp][0], acc[1][2*ntp][1], acc[1][2*ntp][2], acc[1][2*ntp][3],
                            a[1][0], a[1][1], a[1][2], a[1][3], r0, r1);
                    mma_f16(acc[0][2*ntp+1][0], acc[0][2*ntp+1][1], acc[0][2*ntp+1][2], acc[0][2*ntp+1][3],
                            a[0][0], a[0][1], a[0][2], a[0][3], r2, r3);
                    mma_f16(acc[1][2*ntp+1][0], acc[1][2*ntp+1][1], acc[1][2*ntp+1][2], acc[1][2*ntp+1][3],
                            a[1][0], a[1][1], a[1][2], a[1][3], r2, r3);
                }
            }
        }
        if (ch + 1 < 16) CP_WAIT0();
        __syncthreads();
    }

    // ---- epilogue: fp16 round; k/q row-major, v transposed ----
#pragma unroll
    for (int mi = 0; mi < 2; mi++) {
#pragma unroll
        for (int nt = 0; nt < 12; nt++) {
            int gr = m0 + wrow * 32 + mi * 16 + lq;
            int gh = wcol * 96 + nt * 8 + 2 * lk;
            int head = gh >> 6;
            int hc   = gh & 63;
            if (head < 2) {
                __half* op = head ? g_qh : g_kh;
                *(u32*)(op + (size_t)gr * H_ + hc)       = pack16(acc[mi][nt][1], acc[mi][nt][0]);
                *(u32*)(op + (size_t)(gr + 8) * H_ + hc) = pack16(acc[mi][nt][3], acc[mi][nt][2]);
            } else {
                g_vt[(size_t)hc * BT_ + gr]           = __float2half_rn(acc[mi][nt][0]);
                g_vt[(size_t)(hc + 1) * BT_ + gr]     = __float2half_rn(acc[mi][nt][1]);
                g_vt[(size_t)hc * BT_ + gr + 8]       = __float2half_rn(acc[mi][nt][2]);
                g_vt[(size_t)(hc + 1) * BT_ + gr + 8] = __float2half_rn(acc[mi][nt][3]);
            }
        }
    }
}

// =================================================================
// Kernel 2: attention (R9 config). 128-thread CTAs, 4 warps x 32
//   q-rows, occ 3. 4-way quarter split-K, 64-key tiles, double-
//   buffered cp.async, ldmatrix, ex2 softmax with mask-free fast
//   path, ones-column lsum MMA. 512 CTAs: (b, mblk, quarter).
// =================================================================
#define KTILE 64
#define AST 36
#define STG_WORDS (KTILE * AST * 2)
#define STG_BYTES (STG_WORDS * 4)
#define ATTN_SMEM (STG_BYTES * 2)

__global__ void __launch_bounds__(128, 3) attn_mma(int dummy)
{
    extern __shared__ u32 smw[];
    const u32 smb = smem_u32(smw);

    const int tid  = threadIdx.x;
    const int w    = tid >> 5;
    const int lane = tid & 31;
    const int lq   = lane >> 2;
    const int lk   = lane & 3;
    const int grp  = lane >> 3;
    const int lrow = lane & 7;

    const int part = blockIdx.x & 3;
    const int pid  = blockIdx.x >> 2;
    const int b    = pid & 3;
    const int mblk = 31 - (pid >> 2);      // heavy first
    const int m0   = mblk * 128;

    const int nkt = min(2 * mblk + 3, T_ / KTILE);
    const int t_beg = (nkt * part) >> 2;
    const int t_end = (nkt * (part + 1)) >> 2;

    const int qbase = m0 + w * 32;
    const int qa0   = qbase + lq;

    const u32 lmb = (u32)(((((grp >> 1) * 8 + lrow) * AST) + (grp & 1) * 4) * 4);
    const u32 bone = (lq == 0) ? 0x3C003C00u : 0u;

    // ---- Q A-frags fp16, 4 k-steps x 2 row-halves ----
    u32 qf[2][4][4];
#pragma unroll
    for (int mi = 0; mi < 2; mi++) {
        const u32* qp = (const u32*)(g_qh + ((size_t)b * T_ + qa0 + mi * 16) * H_) + lk;
#pragma unroll
        for (int ks = 0; ks < 4; ks++) {
            qf[mi][ks][0] = qp[ks * 8];
            qf[mi][ks][1] = qp[8 * 32 + ks * 8];
            qf[mi][ks][2] = qp[ks * 8 + 4];
            qf[mi][ks][3] = qp[8 * 32 + ks * 8 + 4];
        }
    }

    float oc[2][9][4];     // [..][8] = lsum column accumulator
#pragma unroll
    for (int mi = 0; mi < 2; mi++)
#pragma unroll
        for (int i = 0; i < 9; i++)
#pragma unroll
            for (int j = 0; j < 4; j++) oc[mi][i][j] = 0.0f;

#define ATTN_FILL(STG, T) do {                                               \
    const __half* kg_ = g_kh + ((size_t)b * T_ + (size_t)(T) * KTILE) * H_;  \
    const __half* vg_ = g_vt + (size_t)b * T_ + (size_t)(T) * KTILE;         \
    u32 base_ = smb + (u32)(STG) * STG_BYTES;                                \
    _Pragma("unroll")                                                        \
    for (int i_ = 0; i_ < 4; i_++) {                                         \
        int idx_ = tid + i_ * 128;                                           \
        int r_ = idx_ >> 3, c8_ = idx_ & 7;                                  \
        CP16(base_ + (u32)(r_ * AST + c8_ * 4) * 4,                          \
             (const void*)(kg_ + (size_t)r_ * H_ + c8_ * 8));                \
        CP16(base_ + (u32)(KTILE * AST + r_ * AST + c8_ * 4) * 4,            \
             (const void*)(vg_ + (size_t)r_ * BT_ + c8_ * 8));               \
    }                                                                        \
    CP_COMMIT();                                                             \
} while (0)

    if (t_beg < t_end) ATTN_FILL(t_beg & 1, t_beg);

    for (int t = t_beg; t < t_end; t++) {
        const int j0 = t * KTILE;
        const bool pre = (t + 1 < t_end);
        if (pre) {
            ATTN_FILL((t + 1) & 1, t + 1);
            CP_WAIT1();
        } else {
            CP_WAIT0();
        }
        __syncthreads();

        const u32 kbyte = smb + (u32)(t & 1) * STG_BYTES;
        const u32 vbyte = kbyte + (u32)(KTILE * AST * 4);

        const int ktmax = min(3, (qbase + 32 - j0) >> 4);
        for (int kt = 0; kt <= ktmax; kt++) {
            // ---- S c-frags: 16 keys (2 groups of 8) x 2 row-halves ----
            float sg[2][2][4];
#pragma unroll
            for (int g = 0; g < 2; g++)
#pragma unroll
                for (int mi = 0; mi < 2; mi++)
#pragma unroll
                    for (int e = 0; e < 4; e++) sg[g][mi][e] = 0.0f;
#pragma unroll
            for (int ks = 0; ks < 4; ks++) {
                u32 kb0, kb1, kb2, kb3;
                LDSM4(kb0, kb1, kb2, kb3,
                      kbyte + lmb + (u32)(kt * 16 * AST * 4 + ks * 32));
                mma_f16(sg[0][0][0], sg[0][0][1], sg[0][0][2], sg[0][0][3],
                        qf[0][ks][0], qf[0][ks][1], qf[0][ks][2], qf[0][ks][3], kb0, kb1);
                mma_f16(sg[0][1][0], sg[0][1][1], sg[0][1][2], sg[0][1][3],
                        qf[1][ks][0], qf[1][ks][1], qf[1][ks][2], qf[1][ks][3], kb0, kb1);
                mma_f16(sg[1][0][0], sg[1][0][1], sg[1][0][2], sg[1][0][3],
                        qf[0][ks][0], qf[0][ks][1], qf[0][ks][2], qf[0][ks][3], kb2, kb3);
                mma_f16(sg[1][1][0], sg[1][1][1], sg[1][1][2], sg[1][1][3],
                        qf[1][ks][0], qf[1][ks][1], qf[1][ks][2], qf[1][ks][3], kb2, kb3);
            }

            // ---- softmax: mask-free fast path when fully valid ----
            u32 pa[2][4];
            const int cb = j0 + kt * 16;
            if (cb + 14 <= qbase) {
#pragma unroll
                for (int mi = 0; mi < 2; mi++)
#pragma unroll
                    for (int g = 0; g < 2; g++) {
                        pa[mi][2 * g]     = ex2h2(sg[g][mi][1] * LOG2E64, sg[g][mi][0] * LOG2E64);
                        pa[mi][2 * g + 1] = ex2h2(sg[g][mi][3] * LOG2E64, sg[g][mi][2] * LOG2E64);
                    }
            } else {
#pragma unroll
                for (int mi = 0; mi < 2; mi++) {
                    const int ra = qa0 + mi * 16;
                    const int rb = ra + 8;
#pragma unroll
                    for (int g = 0; g < 2; g++) {
                        const int jb = cb + g * 8 + 2 * lk;
                        float e0 = (jb     <= ra + 1) ? sg[g][mi][0] * LOG2E64 : NEGBIG;
                        float e1 = (jb + 1 <= ra + 1) ? sg[g][mi][1] * LOG2E64 : NEGBIG;
                        float e2 = (jb     <= rb + 1) ? sg[g][mi][2] * LOG2E64 : NEGBIG;
                        float e3 = (jb + 1 <= rb + 1) ? sg[g][mi][3] * LOG2E64 : NEGBIG;
                        pa[mi][2 * g]     = ex2h2(e1, e0);
                        pa[mi][2 * g + 1] = ex2h2(e3, e2);
                    }
                }
            }

            // ---- O += P V ; lsum via ones-column MMA ----
#pragma unroll
            for (int otp = 0; otp < 4; otp++) {
                u32 v0, v1, v2, v3;
                LDSM4(v0, v1, v2, v3,
                      vbyte + lmb + (u32)(otp * 16 * AST * 4 + kt * 32));
                mma_f16(oc[0][2*otp][0], oc[0][2*otp][1], oc[0][2*otp][2], oc[0][2*otp][3],
                        pa[0][0], pa[0][1], pa[0][2], pa[0][3], v0, v1);
                mma_f16(oc[1][2*otp][0], oc[1][2*otp][1], oc[1][2*otp][2], oc[1][2*otp][3],
                        pa[1][0], pa[1][1], pa[1][2], pa[1][3], v0, v1);
                mma_f16(oc[0][2*otp+1][0], oc[0][2*otp+1][1], oc[0][2*otp+1][2], oc[0][2*otp+1][3],
                        pa[0][0], pa[0][1], pa[0][2], pa[0][3], v2, v3);
                mma_f16(oc[1][2*otp+1][0], oc[1][2*otp+1][1], oc[1][2*otp+1][2], oc[1][2*otp+1][3],
                        pa[1][0], pa[1][1], pa[1][2], pa[1][3], v2, v3);
            }
            mma_f16(oc[0][8][0], oc[0][8][1], oc[0][8][2], oc[0][8][3],
                    pa[0][0], pa[0][1], pa[0][2], pa[0][3], bone, bone);
            mma_f16(oc[1][8][0], oc[1][8][1], oc[1][8][2], oc[1][8][3],
                    pa[1][0], pa[1][1], pa[1][2], pa[1][3], bone, bone);
        }
        __syncthreads();
    }

    // ---- write partial lsum (column 0 of ones-MMA C-frag) ----
    float* lp = g_l[part];
    if (lk == 0) {
        lp[(size_t)b * T_ + qa0]      = oc[0][8][0];
        lp[(size_t)b * T_ + qa0 + 8]  = oc[0][8][2];
        lp[(size_t)b * T_ + qa0 + 16] = oc[1][8][0];
        lp[(size_t)b * T_ + qa0 + 24] = oc[1][8][2];
    }

    // ---- write partial O ----
    float* pp = g_p[part];
#pragma unroll
    for (int mi = 0; mi < 2; mi++) {
        float* ra = pp + ((size_t)b * T_ + qa0 + mi * 16) * H_ + 2 * lk;
        float* rb = ra + (size_t)8 * H_;
#pragma unroll
        for (int ot = 0; ot < 8; ot++) {
            *(float2*)(ra + ot * 8) = make_float2(oc[mi][ot][0], oc[mi][ot][1]);
            *(float2*)(rb + ot * 8) = make_float2(oc[mi][ot][2], oc[mi][ot][3]);
        }
    }
    (void)dummy;
}

// =================================================================
// Kernel 3: combine 4 quarters + normalize.
// =================================================================
__global__ void __launch_bounds__(256) norm_out(float* __restrict__ out)
{
    int i4 = blockIdx.x * 256 + threadIdx.x;
    int row = i4 >> 4;
    float inv = 1.0f / (g_l[0][row] + g_l[1][row] + g_l[2][row] + g_l[3][row]);
    float4 a = ((const float4*)g_p[0])[i4];
    float4 c = ((const float4*)g_p[1])[i4];
    float4 d = ((const float4*)g_p[2])[i4];
    float4 e = ((const float4*)g_p[3])[i4];
    float4 o;
    o.x = (a.x + c.x + d.x + e.x) * inv;
    o.y = (a.y + c.y + d.y + e.y) * inv;
    o.z = (a.z + c.z + d.z + e.z) * inv;
    o.w = (a.w + c.w + d.w + e.w) * inv;
    ((float4*)out)[i4] = o;
}

// =================================================================
// launch
// =================================================================
extern "C" void kernel_launch(void* const* d_in, const int* in_sizes, int n_in,
                              void* d_out, int out_size)
{
    const float* x  = (const float*)d_in[0];
    const float* Wk = (const float*)d_in[1];
    const float* Wq = (const float*)d_in[2];
    const float* Wv = (const float*)d_in[3];
    float* out = (float*)d_out;

    (void)in_sizes; (void)n_in; (void)out_size;

    cudaFuncSetAttribute(proj_mma, cudaFuncAttributeMaxDynamicSharedMemorySize, PROJ_SMEM);
    cudaFuncSetAttribute(attn_mma, cudaFuncAttributeMaxDynamicSharedMemorySize, ATTN_SMEM);

    w_cvt<<<384, 256>>>(Wk, Wq, Wv);
    proj_mma<<<BT_ / 128, 256, PROJ_SMEM>>>(x);
    attn_mma<<<512, 128, ATTN_SMEM>>>(0);
    norm_out<<<(BT_ * H_ / 4) / 256, 256>>>(out);
}

// round 15
// speedup vs baseline: 1.2128x; 1.0137x over previous
#include <cuda_runtime.h>
#include <cuda_fp16.h>
#include <cstdint>

// Problem constants
#define B_  4
#define T_  4096
#define C_  1024
#define H_  64
#define BT_ (B_*T_)

typedef unsigned long long u64;
typedef unsigned int u32;

// Scratch — device globals, no allocation.
__device__ __half g_kh[(size_t)BT_ * H_];   // k, fp16 [b][t][h]
__device__ __half g_qh[(size_t)BT_ * H_];   // q, fp16 [b][t][h]
__device__ __half g_vt[(size_t)H_ * BT_];   // v^T, fp16 [h][b*T+t]
__device__ __half g_wh[192 * C_];           // fp16 W (k|q|v rows)
__device__ __half g_ph[4][(size_t)BT_ * H_]; // partial O per key-quarter (fp16)
__device__ float  g_l[4][(size_t)BT_];      // partial lsum per quarter (fp32)

// ---------------- helpers ----------------
__device__ __forceinline__ u32 pack16(float hi, float lo) {
    u32 d; asm("cvt.rn.f16x2.f32 %0, %1, %2;" : "=r"(d) : "f"(hi), "f"(lo)); return d;
}
__device__ __forceinline__ u32 ex2h2(float hi, float lo) {
    u32 x = pack16(hi, lo);
    u32 y; asm("ex2.approx.f16x2 %0, %1;" : "=r"(y) : "r"(x));
    return y;
}
__device__ __forceinline__ void mma_f16(
    float& d0, float& d1, float& d2, float& d3,
    u32 a0, u32 a1, u32 a2, u32 a3, u32 b0, u32 b1)
{
    asm volatile(
        "mma.sync.aligned.m16n8k16.row.col.f32.f16.f16.f32 "
        "{%0,%1,%2,%3}, {%4,%5,%6,%7}, {%8,%9}, {%0,%1,%2,%3};"
        : "+f"(d0), "+f"(d1), "+f"(d2), "+f"(d3)
        : "r"(a0), "r"(a1), "r"(a2), "r"(a3), "r"(b0), "r"(b1));
}
__device__ __forceinline__ u32 smem_u32(const void* p) {
    u32 a;
    asm("{ .reg .u64 t; cvta.to.shared.u64 t, %1; cvt.u32.u64 %0, t; }" : "=r"(a) : "l"(p));
    return a;
}
#define LDSM4(R0, R1, R2, R3, A) \
    asm volatile("ldmatrix.sync.aligned.m8n8.x4.shared.b16 {%0,%1,%2,%3}, [%4];" \
        : "=r"(R0), "=r"(R1), "=r"(R2), "=r"(R3) : "r"(A))
#define CP16(dst, src) asm volatile("cp.async.ca.shared.global [%0], [%1], 16;" :: "r"(dst), "l"(src) : "memory")
#define CP_COMMIT()    asm volatile("cp.async.commit_group;" ::: "memory")
#define CP_WAIT0()     asm volatile("cp.async.wait_group 0;" ::: "memory")
#define CP_WAIT1()     asm volatile("cp.async.wait_group 1;" ::: "memory")

#define LOG2E64 0.02254211001389006f    /* log2(e)/64 */
#define NEGBIG  (-1e30f)

// =================================================================
// Kernel 0: convert W (Wk|Wq|Wv) to fp16 (384 CTAs).
// =================================================================
__global__ void __launch_bounds__(256) w_cvt(
    const float* __restrict__ Wk, const float* __restrict__ Wq,
    const float* __restrict__ Wv)
{
    int f = blockIdx.x * 256 + threadIdx.x;       // float2 index
    int head = f >> 15;
    int off  = f & 32767;
    const float2* src = (const float2*)(head == 0 ? Wk : (head == 1 ? Wq : Wv));
    float2 v = src[off];
    ((u32*)g_wh)[f] = pack16(v.y, v.x);
}

// =================================================================
// Kernel 1: fused QKV projection, fp16 mma + ldmatrix (unchanged).
// =================================================================
#define PST 36                                   // u32 stride per row
#define PROJ_STAGE ((128 + 192) * PST)
#define PROJ_SMEM  (PROJ_STAGE * 2 * 4)

__global__ void __launch_bounds__(256, 1) proj_mma(const float* __restrict__ x)
{
    extern __shared__ u32 psm[];
    const u32 smb = smem_u32(psm);

    const int tid  = threadIdx.x;
    const int w    = tid >> 5;
    const int lane = tid & 31;
    const int lq   = lane >> 2;
    const int lk   = lane & 3;
    const int grp  = lane >> 3;
    const int lrow = lane & 7;
    const int wrow = w >> 1;
    const int wcol = w & 1;
    const int m0   = blockIdx.x * 128;

    const u32 abase = (u32)((((grp & 1) * 8 + lrow) * PST + (grp >> 1) * 4) * 4);
    const u32 bbase = (u32)((((grp >> 1) * 8 + lrow) * PST + (grp & 1) * 4) * 4);
    const u32 xwarp = (u32)(wrow * 32 * PST * 4);
    const u32 wwarp = (u32)((128 + wcol * 96) * PST * 4);

    float acc[2][12][4];
#pragma unroll
    for (int mi = 0; mi < 2; mi++)
#pragma unroll
        for (int nt = 0; nt < 12; nt++)
#pragma unroll
            for (int e = 0; e < 4; e++) acc[mi][nt][e] = 0.0f;

#define PROJ_FILL(SB, CH) do {                                               \
    u32* xs_ = (SB);                                                         \
    u32  wsa_ = smem_u32((SB) + 128 * PST);                                  \
    _Pragma("unroll")                                                        \
    for (int i_ = 0; i_ < 6; i_++) {                                         \
        int idx_ = tid + i_ * 256;                                           \
        int r_ = idx_ >> 3, c8_ = idx_ & 7;                                  \
        CP16(wsa_ + (u32)(r_ * PST + c8_ * 4) * 4,                           \
             (const void*)(g_wh + (size_t)r_ * C_ + (CH) * 64 + c8_ * 8));   \
    }                                                                        \
    _Pragma("unroll")                                                        \
    for (int i_ = 0; i_ < 8; i_++) {                                         \
        int idx_ = tid + i_ * 256;                                           \
        int r_ = idx_ >> 4, c4_ = idx_ & 15;                                 \
        float4 v_ = *(const float4*)(x + (size_t)(m0 + r_) * C_ + (CH) * 64 + c4_ * 4); \
        uint2 u_;                                                            \
        u_.x = pack16(v_.y, v_.x);                                           \
        u_.y = pack16(v_.w, v_.z);                                           \
        *(uint2*)(xs_ + r_ * PST + c4_ * 2) = u_;                            \
    }                                                                        \
    CP_COMMIT();                                                             \
} while (0)

    PROJ_FILL(psm, 0);
    CP_WAIT0();
    __syncthreads();

    for (int ch = 0; ch < 16; ch++) {
        const int cur = ch & 1;
        if (ch + 1 < 16) {
            u32* nb = psm + ((ch + 1) & 1) * PROJ_STAGE;
            PROJ_FILL(nb, ch + 1);
        }
        {
            const u32 sbyte = smb + (u32)cur * (PROJ_STAGE * 4);
#pragma unroll
            for (int ks = 0; ks < 4; ks++) {
                u32 a[2][4];
                LDSM4(a[0][0], a[0][1], a[0][2], a[0][3],
                      sbyte + xwarp + abase + (u32)(ks * 32));
                LDSM4(a[1][0], a[1][1], a[1][2], a[1][3],
                      sbyte + xwarp + abase + (u32)(ks * 32 + 16 * PST * 4));
#pragma unroll
                for (int ntp = 0; ntp < 6; ntp++) {
                    u32 r0, r1, r2, r3;
                    LDSM4(r0, r1, r2, r3,
                          sbyte + wwarp + bbase + (u32)(ntp * 16 * PST * 4 + ks * 32));
                    mma_f16(acc[0][2*ntp][0], acc[0][2*ntp][1], acc[0][2*ntp][2], acc[0][2*ntp][3],
                            a[0][0], a[0][1], a[0][2], a[0][3], r0, r1);
                    mma_f16(acc[1][2*ntp][0], acc[1][2*ntp][1], acc[1][2*ntp][2], acc[1][2*ntp][3],
                            a[1][0], a[1][1], a[1][2], a[1][3], r0, r1);
                    mma_f16(acc[0][2*ntp+1][0], acc[0][2*ntp+1][1], acc[0][2*ntp+1][2], acc[0][2*ntp+1][3],
                            a[0][0], a[0][1], a[0][2], a[0][3], r2, r3);
                    mma_f16(acc[1][2*ntp+1][0], acc[1][2*ntp+1][1], acc[1][2*ntp+1][2], acc[1][2*ntp+1][3],
                            a[1][0], a[1][1], a[1][2], a[1][3], r2, r3);
                }
            }
        }
        if (ch + 1 < 16) CP_WAIT0();
        __syncthreads();
    }

    // ---- epilogue: fp16 round; k/q row-major, v transposed ----
#pragma unroll
    for (int mi = 0; mi < 2; mi++) {
#pragma unroll
        for (int nt = 0; nt < 12; nt++) {
            int gr = m0 + wrow * 32 + mi * 16 + lq;
            int gh = wcol * 96 + nt * 8 + 2 * lk;
            int head = gh >> 6;
            int hc   = gh & 63;
            if (head < 2) {
                __half* op = head ? g_qh : g_kh;
                *(u32*)(op + (size_t)gr * H_ + hc)       = pack16(acc[mi][nt][1], acc[mi][nt][0]);
                *(u32*)(op + (size_t)(gr + 8) * H_ + hc) = pack16(acc[mi][nt][3], acc[mi][nt][2]);
            } else {
                g_vt[(size_t)hc * BT_ + gr]           = __float2half_rn(acc[mi][nt][0]);
                g_vt[(size_t)(hc + 1) * BT_ + gr]     = __float2half_rn(acc[mi][nt][1]);
                g_vt[(size_t)hc * BT_ + gr + 8]       = __float2half_rn(acc[mi][nt][2]);
                g_vt[(size_t)(hc + 1) * BT_ + gr + 8] = __float2half_rn(acc[mi][nt][3]);
            }
        }
    }
}

// =================================================================
// Kernel 2: attention (R14 config, fp16 partial-O stores).
//   128-thread CTAs, 4 warps x 32 q-rows, occ 3. 4-way split-K,
//   64-key tiles, double-buffered cp.async, ldmatrix, ex2 softmax
//   (mask-free fast path), ones-column lsum MMA.
// =================================================================
#define KTILE 64
#define AST 36
#define STG_WORDS (KTILE * AST * 2)
#define STG_BYTES (STG_WORDS * 4)
#define ATTN_SMEM (STG_BYTES * 2)

__global__ void __launch_bounds__(128, 3) attn_mma(int dummy)
{
    extern __shared__ u32 smw[];
    const u32 smb = smem_u32(smw);

    const int tid  = threadIdx.x;
    const int w    = tid >> 5;
    const int lane = tid & 31;
    const int lq   = lane >> 2;
    const int lk   = lane & 3;
    const int grp  = lane >> 3;
    const int lrow = lane & 7;

    const int part = blockIdx.x & 3;
    const int pid  = blockIdx.x >> 2;
    const int b    = pid & 3;
    const int mblk = 31 - (pid >> 2);      // heavy first
    const int m0   = mblk * 128;

    const int nkt = min(2 * mblk + 3, T_ / KTILE);
    const int t_beg = (nkt * part) >> 2;
    const int t_end = (nkt * (part + 1)) >> 2;

    const int qbase = m0 + w * 32;
    const int qa0   = qbase + lq;

    const u32 lmb = (u32)(((((grp >> 1) * 8 + lrow) * AST) + (grp & 1) * 4) * 4);
    const u32 bone = (lq == 0) ? 0x3C003C00u : 0u;

    // ---- Q A-frags fp16, 4 k-steps x 2 row-halves ----
    u32 qf[2][4][4];
#pragma unroll
    for (int mi = 0; mi < 2; mi++) {
        const u32* qp = (const u32*)(g_qh + ((size_t)b * T_ + qa0 + mi * 16) * H_) + lk;
#pragma unroll
        for (int ks = 0; ks < 4; ks++) {
            qf[mi][ks][0] = qp[ks * 8];
            qf[mi][ks][1] = qp[8 * 32 + ks * 8];
            qf[mi][ks][2] = qp[ks * 8 + 4];
            qf[mi][ks][3] = qp[8 * 32 + ks * 8 + 4];
        }
    }

    float oc[2][9][4];     // [..][8] = lsum column accumulator
#pragma unroll
    for (int mi = 0; mi < 2; mi++)
#pragma unroll
        for (int i = 0; i < 9; i++)
#pragma unroll
            for (int j = 0; j < 4; j++) oc[mi][i][j] = 0.0f;

#define ATTN_FILL(STG, T) do {                                               \
    const __half* kg_ = g_kh + ((size_t)b * T_ + (size_t)(T) * KTILE) * H_;  \
    const __half* vg_ = g_vt + (size_t)b * T_ + (size_t)(T) * KTILE;         \
    u32 base_ = smb + (u32)(STG) * STG_BYTES;                                \
    _Pragma("unroll")                                                        \
    for (int i_ = 0; i_ < 4; i_++) {                                         \
        int idx_ = tid + i_ * 128;                                           \
        int r_ = idx_ >> 3, c8_ = idx_ & 7;                                  \
        CP16(base_ + (u32)(r_ * AST + c8_ * 4) * 4,                          \
             (const void*)(kg_ + (size_t)r_ * H_ + c8_ * 8));                \
        CP16(base_ + (u32)(KTILE * AST + r_ * AST + c8_ * 4) * 4,            \
             (const void*)(vg_ + (size_t)r_ * BT_ + c8_ * 8));               \
    }                                                                        \
    CP_COMMIT();                                                             \
} while (0)

    if (t_beg < t_end) ATTN_FILL(t_beg & 1, t_beg);

    for (int t = t_beg; t < t_end; t++) {
        const int j0 = t * KTILE;
        const bool pre = (t + 1 < t_end);
        if (pre) {
            ATTN_FILL((t + 1) & 1, t + 1);
            CP_WAIT1();
        } else {
            CP_WAIT0();
        }
        __syncthreads();

        const u32 kbyte = smb + (u32)(t & 1) * STG_BYTES;
        const u32 vbyte = kbyte + (u32)(KTILE * AST * 4);

        const int ktmax = min(3, (qbase + 32 - j0) >> 4);
        for (int kt = 0; kt <= ktmax; kt++) {
            // ---- S c-frags: 16 keys (2 groups of 8) x 2 row-halves ----
            float sg[2][2][4];
#pragma unroll
            for (int g = 0; g < 2; g++)
#pragma unroll
                for (int mi = 0; mi < 2; mi++)
#pragma unroll
                    for (int e = 0; e < 4; e++) sg[g][mi][e] = 0.0f;
#pragma unroll
            for (int ks = 0; ks < 4; ks++) {
                u32 kb0, kb1, kb2, kb3;
                LDSM4(kb0, kb1, kb2, kb3,
                      kbyte + lmb + (u32)(kt * 16 * AST * 4 + ks * 32));
                mma_f16(sg[0][0][0], sg[0][0][1], sg[0][0][2], sg[0][0][3],
                        qf[0][ks][0], qf[0][ks][1], qf[0][ks][2], qf[0][ks][3], kb0, kb1);
                mma_f16(sg[0][1][0], sg[0][1][1], sg[0][1][2], sg[0][1][3],
                        qf[1][ks][0], qf[1][ks][1], qf[1][ks][2], qf[1][ks][3], kb0, kb1);
                mma_f16(sg[1][0][0], sg[1][0][1], sg[1][0][2], sg[1][0][3],
                        qf[0][ks][0], qf[0][ks][1], qf[0][ks][2], qf[0][ks][3], kb2, kb3);
                mma_f16(sg[1][1][0], sg[1][1][1], sg[1][1][2], sg[1][1][3],
                        qf[1][ks][0], qf[1][ks][1], qf[1][ks][2], qf[1][ks][3], kb2, kb3);
            }

            // ---- softmax: mask-free fast path when fully valid ----
            u32 pa[2][4];
            const int cb = j0 + kt * 16;
            if (cb + 14 <= qbase) {
#pragma unroll
                for (int mi = 0; mi < 2; mi++)
#pragma unroll
                    for (int g = 0; g < 2; g++) {
                        pa[mi][2 * g]     = ex2h2(sg[g][mi][1] * LOG2E64, sg[g][mi][0] * LOG2E64);
                        pa[mi][2 * g + 1] = ex2h2(sg[g][mi][3] * LOG2E64, sg[g][mi][2] * LOG2E64);
                    }
            } else {
#pragma unroll
                for (int mi = 0; mi < 2; mi++) {
                    const int ra = qa0 + mi * 16;
                    const int rb = ra + 8;
#pragma unroll
                    for (int g = 0; g < 2; g++) {
                        const int jb = cb + g * 8 + 2 * lk;
                        float e0 = (jb     <= ra + 1) ? sg[g][mi][0] * LOG2E64 : NEGBIG;
                        float e1 = (jb + 1 <= ra + 1) ? sg[g][mi][1] * LOG2E64 : NEGBIG;
                        float e2 = (jb     <= rb + 1) ? sg[g][mi][2] * LOG2E64 : NEGBIG;
                        float e3 = (jb + 1 <= rb + 1) ? sg[g][mi][3] * LOG2E64 : NEGBIG;
                        pa[mi][2 * g]     = ex2h2(e1, e0);
                        pa[mi][2 * g + 1] = ex2h2(e3, e2);
                    }
                }
            }

            // ---- O += P V ; lsum via ones-column MMA ----
#pragma unroll
            for (int otp = 0; otp < 4; otp++) {
                u32 v0, v1, v2, v3;
                LDSM4(v0, v1, v2, v3,
                      vbyte + lmb + (u32)(otp * 16 * AST * 4 + kt * 32));
                mma_f16(oc[0][2*otp][0], oc[0][2*otp][1], oc[0][2*otp][2], oc[0][2*otp][3],
                        pa[0][0], pa[0][1], pa[0][2], pa[0][3], v0, v1);
                mma_f16(oc[1][2*otp][0], oc[1][2*otp][1], oc[1][2*otp][2], oc[1][2*otp][3],
                        pa[1][0], pa[1][1], pa[1][2], pa[1][3], v0, v1);
                mma_f16(oc[0][2*otp+1][0], oc[0][2*otp+1][1], oc[0][2*otp+1][2], oc[0][2*otp+1][3],
                        pa[0][0], pa[0][1], pa[0][2], pa[0][3], v2, v3);
                mma_f16(oc[1][2*otp+1][0], oc[1][2*otp+1][1], oc[1][2*otp+1][2], oc[1][2*otp+1][3],
                        pa[1][0], pa[1][1], pa[1][2], pa[1][3], v2, v3);
            }
            mma_f16(oc[0][8][0], oc[0][8][1], oc[0][8][2], oc[0][8][3],
                    pa[0][0], pa[0][1], pa[0][2], pa[0][3], bone, bone);
            mma_f16(oc[1][8][0], oc[1][8][1], oc[1][8][2], oc[1][8][3],
                    pa[1][0], pa[1][1], pa[1][2], pa[1][3], bone, bone);
        }
        __syncthreads();
    }

    // ---- write partial lsum (fp32) ----
    float* lp = g_l[part];
    if (lk == 0) {
        lp[(size_t)b * T_ + qa0]      = oc[0][8][0];
        lp[(size_t)b * T_ + qa0 + 8]  = oc[0][8][2];
        lp[(size_t)b * T_ + qa0 + 16] = oc[1][8][0];
        lp[(size_t)b * T_ + qa0 + 24] = oc[1][8][2];
    }

    // ---- write partial O (fp16 packed) ----
    __half* pp = g_ph[part];
#pragma unroll
    for (int mi = 0; mi < 2; mi++) {
        __half* ra = pp + ((size_t)b * T_ + qa0 + mi * 16) * H_ + 2 * lk;
        __half* rb = ra + (size_t)8 * H_;
#pragma unroll
        for (int ot = 0; ot < 8; ot++) {
            *(u32*)(ra + ot * 8) = pack16(oc[mi][ot][1], oc[mi][ot][0]);
            *(u32*)(rb + ot * 8) = pack16(oc[mi][ot][3], oc[mi][ot][2]);
        }
    }
    (void)dummy;
}

// =================================================================
// Kernel 3: combine 4 fp16 quarters + normalize (fp32 math).
// =================================================================
__global__ void __launch_bounds__(256) norm_out(float* __restrict__ out)
{
    int i8 = blockIdx.x * 256 + threadIdx.x;      // 8-half (16B) index
    int row = i8 >> 3;
    float inv = 1.0f / (g_l[0][row] + g_l[1][row] + g_l[2][row] + g_l[3][row]);

    float acc[8];
#pragma unroll
    for (int e = 0; e < 8; e++) acc[e] = 0.0f;
#pragma unroll
    for (int sl = 0; sl < 4; sl++) {
        uint4 pv = ((const uint4*)g_ph[sl])[i8];
        const u32 pw[4] = {pv.x, pv.y, pv.z, pv.w};
#pragma unroll
        for (int q = 0; q < 4; q++) {
            __half2 h2 = *(const __half2*)&pw[q];
            float2 f2 = __half22float2(h2);
            acc[2 * q]     += f2.x;
            acc[2 * q + 1] += f2.y;
        }
    }
    float4 o0, o1;
    o0.x = acc[0] * inv; o0.y = acc[1] * inv; o0.z = acc[2] * inv; o0.w = acc[3] * inv;
    o1.x = acc[4] * inv; o1.y = acc[5] * inv; o1.z = acc[6] * inv; o1.w = acc[7] * inv;
    ((float4*)out)[i8 * 2]     = o0;
    ((float4*)out)[i8 * 2 + 1] = o1;
}

// =================================================================
// launch
// =================================================================
extern "C" void kernel_launch(void* const* d_in, const int* in_sizes, int n_in,
                              void* d_out, int out_size)
{
    const float* x  = (const float*)d_in[0];
    const float* Wk = (const float*)d_in[1];
    const float* Wq = (const float*)d_in[2];
    const float* Wv = (const float*)d_in[3];
    float* out = (float*)d_out;

    (void)in_sizes; (void)n_in; (void)out_size;

    cudaFuncSetAttribute(proj_mma, cudaFuncAttributeMaxDynamicSharedMemorySize, PROJ_SMEM);
    cudaFuncSetAttribute(attn_mma, cudaFuncAttributeMaxDynamicSharedMemorySize, ATTN_SMEM);

    w_cvt<<<384, 256>>>(Wk, Wq, Wv);
    proj_mma<<<BT_ / 128, 256, PROJ_SMEM>>>(x);
    attn_mma<<<512, 128, ATTN_SMEM>>>(0);
    norm_out<<<(BT_ * H_ / 8) / 256, 256>>>(out);
}

// round 16
// speedup vs baseline: 1.2553x; 1.0350x over previous
#include <cuda_runtime.h>
#include <cuda_fp16.h>
#include <cstdint>

// Problem constants
#define B_  4
#define T_  4096
#define C_  1024
#define H_  64
#define BT_ (B_*T_)

typedef unsigned long long u64;
typedef unsigned int u32;

// Scratch — device globals, no allocation.
__device__ __half g_kh[(size_t)BT_ * H_];   // k, fp16 [b][t][h]
__device__ __half g_qh[(size_t)BT_ * H_];   // q*log2e/64, fp16 [b][t][h]
__device__ __half g_vt[(size_t)H_ * BT_];   // v^T, fp16 [h][b*T+t]
__device__ __half g_wh[192 * C_];           // fp16 W (k|q|v rows)
__device__ __half g_ph[4][(size_t)BT_ * H_]; // partial O per key-quarter (fp16)
__device__ float  g_l[4][(size_t)BT_];      // partial lsum per quarter (fp32)

// ---------------- helpers ----------------
__device__ __forceinline__ u32 pack16(float hi, float lo) {
    u32 d; asm("cvt.rn.f16x2.f32 %0, %1, %2;" : "=r"(d) : "f"(hi), "f"(lo)); return d;
}
__device__ __forceinline__ u32 ex2h2(float hi, float lo) {
    u32 x = pack16(hi, lo);
    u32 y; asm("ex2.approx.f16x2 %0, %1;" : "=r"(y) : "r"(x));
    return y;
}
__device__ __forceinline__ void mma_f16(
    float& d0, float& d1, float& d2, float& d3,
    u32 a0, u32 a1, u32 a2, u32 a3, u32 b0, u32 b1)
{
    asm volatile(
        "mma.sync.aligned.m16n8k16.row.col.f32.f16.f16.f32 "
        "{%0,%1,%2,%3}, {%4,%5,%6,%7}, {%8,%9}, {%0,%1,%2,%3};"
        : "+f"(d0), "+f"(d1), "+f"(d2), "+f"(d3)
        : "r"(a0), "r"(a1), "r"(a2), "r"(a3), "r"(b0), "r"(b1));
}
__device__ __forceinline__ u32 smem_u32(const void* p) {
    u32 a;
    asm("{ .reg .u64 t; cvta.to.shared.u64 t, %1; cvt.u32.u64 %0, t; }" : "=r"(a) : "l"(p));
    return a;
}
#define LDSM4(R0, R1, R2, R3, A) \
    asm volatile("ldmatrix.sync.aligned.m8n8.x4.shared.b16 {%0,%1,%2,%3}, [%4];" \
        : "=r"(R0), "=r"(R1), "=r"(R2), "=r"(R3) : "r"(A))
#define CP16(dst, src) asm volatile("cp.async.ca.shared.global [%0], [%1], 16;" :: "r"(dst), "l"(src) : "memory")
#define CP_COMMIT()    asm volatile("cp.async.commit_group;" ::: "memory")
#define CP_WAIT0()     asm volatile("cp.async.wait_group 0;" ::: "memory")
#define CP_WAIT1()     asm volatile("cp.async.wait_group 1;" ::: "memory")

#define LOG2E64 0.02254211001389006f    /* log2(e)/64 */
#define NEGBIG  (-1e30f)

// =================================================================
// Kernel 0: convert W (Wk|Wq|Wv) to fp16 (384 CTAs).
// =================================================================
__global__ void __launch_bounds__(256) w_cvt(
    const float* __restrict__ Wk, const float* __restrict__ Wq,
    const float* __restrict__ Wv)
{
    int f = blockIdx.x * 256 + threadIdx.x;       // float2 index
    int head = f >> 15;
    int off  = f & 32767;
    const float2* src = (const float2*)(head == 0 ? Wk : (head == 1 ? Wq : Wv));
    float2 v = src[off];
    ((u32*)g_wh)[f] = pack16(v.y, v.x);
}

// =================================================================
// Kernel 1: fused QKV projection, fp16 mma + ldmatrix.
//   q output is PRE-SCALED by log2(e)/64 (ex2-domain logits).
// =================================================================
#define PST 36                                   // u32 stride per row
#define PROJ_STAGE ((128 + 192) * PST)
#define PROJ_SMEM  (PROJ_STAGE * 2 * 4)

__global__ void __launch_bounds__(256, 1) proj_mma(const float* __restrict__ x)
{
    extern __shared__ u32 psm[];
    const u32 smb = smem_u32(psm);

    const int tid  = threadIdx.x;
    const int w    = tid >> 5;
    const int lane = tid & 31;
    const int lq   = lane >> 2;
    const int lk   = lane & 3;
    const int grp  = lane >> 3;
    const int lrow = lane & 7;
    const int wrow = w >> 1;
    const int wcol = w & 1;
    const int m0   = blockIdx.x * 128;

    const u32 abase = (u32)((((grp & 1) * 8 + lrow) * PST + (grp >> 1) * 4) * 4);
    const u32 bbase = (u32)((((grp >> 1) * 8 + lrow) * PST + (grp & 1) * 4) * 4);
    const u32 xwarp = (u32)(wrow * 32 * PST * 4);
    const u32 wwarp = (u32)((128 + wcol * 96) * PST * 4);

    float acc[2][12][4];
#pragma unroll
    for (int mi = 0; mi < 2; mi++)
#pragma unroll
        for (int nt = 0; nt < 12; nt++)
#pragma unroll
            for (int e = 0; e < 4; e++) acc[mi][nt][e] = 0.0f;

#define PROJ_FILL(SB, CH) do {                                               \
    u32* xs_ = (SB);                                                         \
    u32  wsa_ = smem_u32((SB) + 128 * PST);                                  \
    _Pragma("unroll")                                                        \
    for (int i_ = 0; i_ < 6; i_++) {                                         \
        int idx_ = tid + i_ * 256;                                           \
        int r_ = idx_ >> 3, c8_ = idx_ & 7;                                  \
        CP16(wsa_ + (u32)(r_ * PST + c8_ * 4) * 4,                           \
             (const void*)(g_wh + (size_t)r_ * C_ + (CH) * 64 + c8_ * 8));   \
    }                                                                        \
    _Pragma("unroll")                                                        \
    for (int i_ = 0; i_ < 8; i_++) {                                         \
        int idx_ = tid + i_ * 256;                                           \
        int r_ = idx_ >> 4, c4_ = idx_ & 15;                                 \
        float4 v_ = *(const float4*)(x + (size_t)(m0 + r_) * C_ + (CH) * 64 + c4_ * 4); \
        uint2 u_;                                                            \
        u_.x = pack16(v_.y, v_.x);                                           \
        u_.y = pack16(v_.w, v_.z);                                           \
        *(uint2*)(xs_ + r_ * PST + c4_ * 2) = u_;                            \
    }                                                                        \
    CP_COMMIT();                                                             \
} while (0)

    PROJ_FILL(psm, 0);
    CP_WAIT0();
    __syncthreads();

    for (int ch = 0; ch < 16; ch++) {
        const int cur = ch & 1;
        if (ch + 1 < 16) {
            u32* nb = psm + ((ch + 1) & 1) * PROJ_STAGE;
            PROJ_FILL(nb, ch + 1);
        }
        {
            const u32 sbyte = smb + (u32)cur * (PROJ_STAGE * 4);
#pragma unroll
            for (int ks = 0; ks < 4; ks++) {
                u32 a[2][4];
                LDSM4(a[0][0], a[0][1], a[0][2], a[0][3],
                      sbyte + xwarp + abase + (u32)(ks * 32));
                LDSM4(a[1][0], a[1][1], a[1][2], a[1][3],
                      sbyte + xwarp + abase + (u32)(ks * 32 + 16 * PST * 4));
#pragma unroll
                for (int ntp = 0; ntp < 6; ntp++) {
                    u32 r0, r1, r2, r3;
                    LDSM4(r0, r1, r2, r3,
                          sbyte + wwarp + bbase + (u32)(ntp * 16 * PST * 4 + ks * 32));
                    mma_f16(acc[0][2*ntp][0], acc[0][2*ntp][1], acc[0][2*ntp][2], acc[0][2*ntp][3],
                            a[0][0], a[0][1], a[0][2], a[0][3], r0, r1);
                    mma_f16(acc[1][2*ntp][0], acc[1][2*ntp][1], acc[1][2*ntp][2], acc[1][2*ntp][3],
                            a[1][0], a[1][1], a[1][2], a[1][3], r0, r1);
                    mma_f16(acc[0][2*ntp+1][0], acc[0][2*ntp+1][1], acc[0][2*ntp+1][2], acc[0][2*ntp+1][3],
                            a[0][0], a[0][1], a[0][2], a[0][3], r2, r3);
                    mma_f16(acc[1][2*ntp+1][0], acc[1][2*ntp+1][1], acc[1][2*ntp+1][2], acc[1][2*ntp+1][3],
                            a[1][0], a[1][1], a[1][2], a[1][3], r2, r3);
                }
            }
        }
        if (ch + 1 < 16) CP_WAIT0();
        __syncthreads();
    }

    // ---- epilogue: fp16 round; k/q row-major (q pre-scaled), v transposed ----
#pragma unroll
    for (int mi = 0; mi < 2; mi++) {
#pragma unroll
        for (int nt = 0; nt < 12; nt++) {
            int gr = m0 + wrow * 32 + mi * 16 + lq;
            int gh = wcol * 96 + nt * 8 + 2 * lk;
            int head = gh >> 6;
            int hc   = gh & 63;
            if (head == 0) {
                *(u32*)(g_kh + (size_t)gr * H_ + hc)       = pack16(acc[mi][nt][1], acc[mi][nt][0]);
                *(u32*)(g_kh + (size_t)(gr + 8) * H_ + hc) = pack16(acc[mi][nt][3], acc[mi][nt][2]);
            } else if (head == 1) {
                *(u32*)(g_qh + (size_t)gr * H_ + hc)       =
                    pack16(acc[mi][nt][1] * LOG2E64, acc[mi][nt][0] * LOG2E64);
                *(u32*)(g_qh + (size_t)(gr + 8) * H_ + hc) =
                    pack16(acc[mi][nt][3] * LOG2E64, acc[mi][nt][2] * LOG2E64);
            } else {
                g_vt[(size_t)hc * BT_ + gr]           = __float2half_rn(acc[mi][nt][0]);
                g_vt[(size_t)(hc + 1) * BT_ + gr]     = __float2half_rn(acc[mi][nt][1]);
                g_vt[(size_t)hc * BT_ + gr + 8]       = __float2half_rn(acc[mi][nt][2]);
                g_vt[(size_t)(hc + 1) * BT_ + gr + 8] = __float2half_rn(acc[mi][nt][3]);
            }
        }
    }
}

// =================================================================
// Kernel 2: attention. Logits arrive pre-scaled (ex2-domain) —
//   softmax is just ex2h2 of the raw S C-frags. Otherwise R15.
// =================================================================
#define KTILE 64
#define AST 36
#define STG_WORDS (KTILE * AST * 2)
#define STG_BYTES (STG_WORDS * 4)
#define ATTN_SMEM (STG_BYTES * 2)

__global__ void __launch_bounds__(128, 3) attn_mma(int dummy)
{
    extern __shared__ u32 smw[];
    const u32 smb = smem_u32(smw);

    const int tid  = threadIdx.x;
    const int w    = tid >> 5;
    const int lane = tid & 31;
    const int lq   = lane >> 2;
    const int lk   = lane & 3;
    const int grp  = lane >> 3;
    const int lrow = lane & 7;

    const int part = blockIdx.x & 3;
    const int pid  = blockIdx.x >> 2;
    const int b    = pid & 3;
    const int mblk = 31 - (pid >> 2);      // heavy first
    const int m0   = mblk * 128;

    const int nkt = min(2 * mblk + 3, T_ / KTILE);
    const int t_beg = (nkt * part) >> 2;
    const int t_end = (nkt * (part + 1)) >> 2;

    const int qbase = m0 + w * 32;
    const int qa0   = qbase + lq;

    const u32 lmb = (u32)(((((grp >> 1) * 8 + lrow) * AST) + (grp & 1) * 4) * 4);
    const u32 bone = (lq == 0) ? 0x3C003C00u : 0u;

    // ---- Q A-frags fp16 (pre-scaled), 4 k-steps x 2 row-halves ----
    u32 qf[2][4][4];
#pragma unroll
    for (int mi = 0; mi < 2; mi++) {
        const u32* qp = (const u32*)(g_qh + ((size_t)b * T_ + qa0 + mi * 16) * H_) + lk;
#pragma unroll
        for (int ks = 0; ks < 4; ks++) {
            qf[mi][ks][0] = qp[ks * 8];
            qf[mi][ks][1] = qp[8 * 32 + ks * 8];
            qf[mi][ks][2] = qp[ks * 8 + 4];
            qf[mi][ks][3] = qp[8 * 32 + ks * 8 + 4];
        }
    }

    float oc[2][9][4];     // [..][8] = lsum column accumulator
#pragma unroll
    for (int mi = 0; mi < 2; mi++)
#pragma unroll
        for (int i = 0; i < 9; i++)
#pragma unroll
            for (int j = 0; j < 4; j++) oc[mi][i][j] = 0.0f;

#define ATTN_FILL(STG, T) do {                                               \
    const __half* kg_ = g_kh + ((size_t)b * T_ + (size_t)(T) * KTILE) * H_;  \
    const __half* vg_ = g_vt + (size_t)b * T_ + (size_t)(T) * KTILE;         \
    u32 base_ = smb + (u32)(STG) * STG_BYTES;                                \
    _Pragma("unroll")                                                        \
    for (int i_ = 0; i_ < 4; i_++) {                                         \
        int idx_ = tid + i_ * 128;                                           \
        int r_ = idx_ >> 3, c8_ = idx_ & 7;                                  \
        CP16(base_ + (u32)(r_ * AST + c8_ * 4) * 4,                          \
             (const void*)(kg_ + (size_t)r_ * H_ + c8_ * 8));                \
        CP16(base_ + (u32)(KTILE * AST + r_ * AST + c8_ * 4) * 4,            \
             (const void*)(vg_ + (size_t)r_ * BT_ + c8_ * 8));               \
    }                                                                        \
    CP_COMMIT();                                                             \
} while (0)

    if (t_beg < t_end) ATTN_FILL(t_beg & 1, t_beg);

    for (int t = t_beg; t < t_end; t++) {
        const int j0 = t * KTILE;
        const bool pre = (t + 1 < t_end);
        if (pre) {
            ATTN_FILL((t + 1) & 1, t + 1);
            CP_WAIT1();
        } else {
            CP_WAIT0();
        }
        __syncthreads();

        const u32 kbyte = smb + (u32)(t & 1) * STG_BYTES;
        const u32 vbyte = kbyte + (u32)(KTILE * AST * 4);

        const int ktmax = min(3, (qbase + 32 - j0) >> 4);
        for (int kt = 0; kt <= ktmax; kt++) {
            // ---- S c-frags: 16 keys (2 groups of 8) x 2 row-halves ----
            float sg[2][2][4];
#pragma unroll
            for (int g = 0; g < 2; g++)
#pragma unroll
                for (int mi = 0; mi < 2; mi++)
#pragma unroll
                    for (int e = 0; e < 4; e++) sg[g][mi][e] = 0.0f;
#pragma unroll
            for (int ks = 0; ks < 4; ks++) {
                u32 kb0, kb1, kb2, kb3;
                LDSM4(kb0, kb1, kb2, kb3,
                      kbyte + lmb + (u32)(kt * 16 * AST * 4 + ks * 32));
                mma_f16(sg[0][0][0], sg[0][0][1], sg[0][0][2], sg[0][0][3],
                        qf[0][ks][0], qf[0][ks][1], qf[0][ks][2], qf[0][ks][3], kb0, kb1);
                mma_f16(sg[0][1][0], sg[0][1][1], sg[0][1][2], sg[0][1][3],
                        qf[1][ks][0], qf[1][ks][1], qf[1][ks][2], qf[1][ks][3], kb0, kb1);
                mma_f16(sg[1][0][0], sg[1][0][1], sg[1][0][2], sg[1][0][3],
                        qf[0][ks][0], qf[0][ks][1], qf[0][ks][2], qf[0][ks][3], kb2, kb3);
                mma_f16(sg[1][1][0], sg[1][1][1], sg[1][1][2], sg[1][1][3],
                        qf[1][ks][0], qf[1][ks][1], qf[1][ks][2], qf[1][ks][3], kb2, kb3);
            }

            // ---- softmax: logits already in ex2 domain ----
            u32 pa[2][4];
            const int cb = j0 + kt * 16;
            if (cb + 14 <= qbase) {
#pragma unroll
                for (int mi = 0; mi < 2; mi++)
#pragma unroll
                    for (int g = 0; g < 2; g++) {
                        pa[mi][2 * g]     = ex2h2(sg[g][mi][1], sg[g][mi][0]);
                        pa[mi][2 * g + 1] = ex2h2(sg[g][mi][3], sg[g][mi][2]);
                    }
            } else {
#pragma unroll
                for (int mi = 0; mi < 2; mi++) {
                    const int ra = qa0 + mi * 16;
                    const int rb = ra + 8;
#pragma unroll
                    for (int g = 0; g < 2; g++) {
                        const int jb = cb + g * 8 + 2 * lk;
                        float e0 = (jb     <= ra + 1) ? sg[g][mi][0] : NEGBIG;
                        float e1 = (jb + 1 <= ra + 1) ? sg[g][mi][1] : NEGBIG;
                        float e2 = (jb     <= rb + 1) ? sg[g][mi][2] : NEGBIG;
                        float e3 = (jb + 1 <= rb + 1) ? sg[g][mi][3] : NEGBIG;
                        pa[mi][2 * g]     = ex2h2(e1, e0);
                        pa[mi][2 * g + 1] = ex2h2(e3, e2);
                    }
                }
            }

            // ---- O += P V ; lsum via ones-column MMA ----
#pragma unroll
            for (int otp = 0; otp < 4; otp++) {
                u32 v0, v1, v2, v3;
                LDSM4(v0, v1, v2, v3,
                      vbyte + lmb + (u32)(otp * 16 * AST * 4 + kt * 32));
                mma_f16(oc[0][2*otp][0], oc[0][2*otp][1], oc[0][2*otp][2], oc[0][2*otp][3],
                        pa[0][0], pa[0][1], pa[0][2], pa[0][3], v0, v1);
                mma_f16(oc[1][2*otp][0], oc[1][2*otp][1], oc[1][2*otp][2], oc[1][2*otp][3],
                        pa[1][0], pa[1][1], pa[1][2], pa[1][3], v0, v1);
                mma_f16(oc[0][2*otp+1][0], oc[0][2*otp+1][1], oc[0][2*otp+1][2], oc[0][2*otp+1][3],
                        pa[0][0], pa[0][1], pa[0][2], pa[0][3], v2, v3);
                mma_f16(oc[1][2*otp+1][0], oc[1][2*otp+1][1], oc[1][2*otp+1][2], oc[1][2*otp+1][3],
                        pa[1][0], pa[1][1], pa[1][2], pa[1][3], v2, v3);
            }
            mma_f16(oc[0][8][0], oc[0][8][1], oc[0][8][2], oc[0][8][3],
                    pa[0][0], pa[0][1], pa[0][2], pa[0][3], bone, bone);
            mma_f16(oc[1][8][0], oc[1][8][1], oc[1][8][2], oc[1][8][3],
                    pa[1][0], pa[1][1], pa[1][2], pa[1][3], bone, bone);
        }
        __syncthreads();
    }

    // ---- write partial lsum (fp32) ----
    float* lp = g_l[part];
    if (lk == 0) {
        lp[(size_t)b * T_ + qa0]      = oc[0][8][0];
        lp[(size_t)b * T_ + qa0 + 8]  = oc[0][8][2];
        lp[(size_t)b * T_ + qa0 + 16] = oc[1][8][0];
        lp[(size_t)b * T_ + qa0 + 24] = oc[1][8][2];
    }

    // ---- write partial O (fp16 packed) ----
    __half* pp = g_ph[part];
#pragma unroll
    for (int mi = 0; mi < 2; mi++) {
        __half* ra = pp + ((size_t)b * T_ + qa0 + mi * 16) * H_ + 2 * lk;
        __half* rb = ra + (size_t)8 * H_;
#pragma unroll
        for (int ot = 0; ot < 8; ot++) {
            *(u32*)(ra + ot * 8) = pack16(oc[mi][ot][1], oc[mi][ot][0]);
            *(u32*)(rb + ot * 8) = pack16(oc[mi][ot][3], oc[mi][ot][2]);
        }
    }
    (void)dummy;
}

// =================================================================
// Kernel 3: combine 4 fp16 quarters + normalize (2 groups/thread).
// =================================================================
__global__ void __launch_bounds__(256) norm_out(float* __restrict__ out)
{
    int base = blockIdx.x * 512 + threadIdx.x;    // two 8-half groups
#pragma unroll
    for (int hgi = 0; hgi < 2; hgi++) {
        int i8 = base + hgi * 256;
        int row = i8 >> 3;
        float inv = 1.0f / (g_l[0][row] + g_l[1][row] + g_l[2][row] + g_l[3][row]);

        float acc[8];
#pragma unroll
        for (int e = 0; e < 8; e++) acc[e] = 0.0f;
#pragma unroll
        for (int sl = 0; sl < 4; sl++) {
            uint4 pv = ((const uint4*)g_ph[sl])[i8];
            const u32 pw[4] = {pv.x, pv.y, pv.z, pv.w};
#pragma unroll
            for (int q = 0; q < 4; q++) {
                __half2 h2 = *(const __half2*)&pw[q];
                float2 f2 = __half22float2(h2);
                acc[2 * q]     += f2.x;
                acc[2 * q + 1] += f2.y;
            }
        }
        float4 o0, o1;
        o0.x = acc[0] * inv; o0.y = acc[1] * inv; o0.z = acc[2] * inv; o0.w = acc[3] * inv;
        o1.x = acc[4] * inv; o1.y = acc[5] * inv; o1.z = acc[6] * inv; o1.w = acc[7] * inv;
        ((float4*)out)[i8 * 2]     = o0;
        ((float4*)out)[i8 * 2 + 1] = o1;
    }
}

// =================================================================
// launch
// =================================================================
extern "C" void kernel_launch(void* const* d_in, const int* in_sizes, int n_in,
                              void* d_out, int out_size)
{
    const float* x  = (const float*)d_in[0];
    const float* Wk = (const float*)d_in[1];
    const float* Wq = (const float*)d_in[2];
    const float* Wv = (const float*)d_in[3];
    float* out = (float*)d_out;

    (void)in_sizes; (void)n_in; (void)out_size;

    cudaFuncSetAttribute(proj_mma, cudaFuncAttributeMaxDynamicSharedMemorySize, PROJ_SMEM);
    cudaFuncSetAttribute(attn_mma, cudaFuncAttributeMaxDynamicSharedMemorySize, ATTN_SMEM);

    w_cvt<<<384, 256>>>(Wk, Wq, Wv);
    proj_mma<<<BT_ / 128, 256, PROJ_SMEM>>>(x);
    attn_mma<<<512, 128, ATTN_SMEM>>>(0);
    norm_out<<<(BT_ * H_ / 16) / 256, 256>>>(out);
}